// round 1
// baseline (speedup 1.0000x reference)
#include <cuda_runtime.h>
#include <cuda_bf16.h>
#include <math.h>

// Problem constants
#define BB   4
#define SS   1024
#define DD   1024
#define HH   16
#define DKK  64
#define DFFN 4096
#define MM   (BB*SS)        // 4096 token rows
#define BH   (BB*HH)        // 64

// ---------------------------------------------------------------------------
// Scratch (device globals: allocation inside kernel_launch is forbidden)
// ---------------------------------------------------------------------------
__device__ float g_q[MM*DD];
__device__ float g_k[MM*DD];
__device__ float g_v[MM*DD];
__device__ float g_attn[MM*DD];
__device__ float g_tmp[MM*DD];
__device__ float g_x1[MM*DD];
__device__ float g_x2[MM*DD];
__device__ float g_scores[(long long)BH*SS*SS];   // 64M floats = 268MB
__device__ float g_hidden[(long long)MM*DFFN];    // 67MB

// ---------------------------------------------------------------------------
// GEMM: C = alpha * (A @ B^T) + bias [, relu]
// A: [M,K] lda ; B(weights): [N,K] ldb ; C: [M,N] ldc
// Batched via blockIdx.z: offset = (z/zdiv)*s1 + (z%zdiv)*s2 per tensor.
// Tiles: BM=128, BN=128, BK=16, 256 threads, 8x8 microtile.
// ---------------------------------------------------------------------------
template<bool RELU>
__global__ void __launch_bounds__(256, 2) gemm_tn(
    const float* __restrict__ A, int lda, long long sA1, long long sA2,
    const float* __restrict__ B, int ldb, long long sB1, long long sB2,
    const float* __restrict__ bias,
    float* __restrict__ C, int ldc, long long sC1, long long sC2,
    int M, int N, int K, float alpha, int zdiv)
{
    __shared__ float As[16][132];
    __shared__ float Bs[16][132];

    int z  = blockIdx.z;
    int zb = z / zdiv, zh = z % zdiv;
    A += zb * sA1 + zh * sA2;
    B += zb * sB1 + zh * sB2;
    C += zb * sC1 + zh * sC2;

    int row0 = blockIdx.y * 128;
    int col0 = blockIdx.x * 128;
    int t  = threadIdx.x;
    int tx = t & 15;        // col group (8 cols)
    int ty = t >> 4;        // row group (8 rows)

    float acc[8][8];
    #pragma unroll
    for (int i = 0; i < 8; i++)
        #pragma unroll
        for (int j = 0; j < 8; j++) acc[i][j] = 0.f;

    for (int k0 = 0; k0 < K; k0 += 16) {
        // Load A tile 128x16 (2 float4 per thread), transpose into As[k][m]
        #pragma unroll
        for (int i = 0; i < 2; i++) {
            int l  = t + i * 256;         // 0..511
            int m  = l >> 2;              // 0..127
            int kq = l & 3;               // 0..3 (float4 within k)
            float4 vv = *(const float4*)(A + (long long)(row0 + m) * lda + k0 + kq * 4);
            As[kq*4+0][m] = vv.x; As[kq*4+1][m] = vv.y;
            As[kq*4+2][m] = vv.z; As[kq*4+3][m] = vv.w;
        }
        // Load B tile 128x16 likewise
        #pragma unroll
        for (int i = 0; i < 2; i++) {
            int l  = t + i * 256;
            int n  = l >> 2;
            int kq = l & 3;
            float4 vv = *(const float4*)(B + (long long)(col0 + n) * ldb + k0 + kq * 4);
            Bs[kq*4+0][n] = vv.x; Bs[kq*4+1][n] = vv.y;
            Bs[kq*4+2][n] = vv.z; Bs[kq*4+3][n] = vv.w;
        }
        __syncthreads();

        #pragma unroll
        for (int k = 0; k < 16; k++) {
            float a[8], b[8];
            *(float4*)(a)   = *(float4*)&As[k][ty*8];
            *(float4*)(a+4) = *(float4*)&As[k][ty*8+4];
            *(float4*)(b)   = *(float4*)&Bs[k][tx*8];
            *(float4*)(b+4) = *(float4*)&Bs[k][tx*8+4];
            #pragma unroll
            for (int i = 0; i < 8; i++)
                #pragma unroll
                for (int j = 0; j < 8; j++)
                    acc[i][j] = fmaf(a[i], b[j], acc[i][j]);
        }
        __syncthreads();
    }

    #pragma unroll
    for (int i = 0; i < 8; i++) {
        int row = row0 + ty * 8 + i;
        #pragma unroll
        for (int j = 0; j < 8; j++) {
            int col = col0 + tx * 8 + j;
            float v = acc[i][j] * alpha;
            if (bias) v += bias[col];
            if (RELU) v = fmaxf(v, 0.f);
            C[(long long)row * ldc + col] = v;
        }
    }
}

// ---------------------------------------------------------------------------
// GEMM NN: C = A @ B   (used for P @ V)
// A: [M,K] lda ; B: [K,N] ldb ; C: [M,N] ldc. Batched like above.
// Tiles: BM=256, BN=64, BK=16, 256 threads, 16x4 microtile.
// ---------------------------------------------------------------------------
__global__ void __launch_bounds__(256, 2) gemm_nn(
    const float* __restrict__ A, int lda, long long sA1, long long sA2,
    const float* __restrict__ B, int ldb, long long sB1, long long sB2,
    float* __restrict__ C, int ldc, long long sC1, long long sC2,
    int M, int N, int K, int zdiv)
{
    __shared__ float As[16][264];
    __shared__ float Bs[16][68];

    int z  = blockIdx.z;
    int zb = z / zdiv, zh = z % zdiv;
    A += zb * sA1 + zh * sA2;
    B += zb * sB1 + zh * sB2;
    C += zb * sC1 + zh * sC2;

    int row0 = blockIdx.y * 256;
    int col0 = blockIdx.x * 64;
    int t  = threadIdx.x;
    int tx = t & 15;    // 4 cols
    int ty = t >> 4;    // 16 rows

    float acc[16][4];
    #pragma unroll
    for (int i = 0; i < 16; i++)
        #pragma unroll
        for (int j = 0; j < 4; j++) acc[i][j] = 0.f;

    for (int k0 = 0; k0 < K; k0 += 16) {
        // A tile 256x16 -> As[k][m] (4 float4 per thread)
        #pragma unroll
        for (int i = 0; i < 4; i++) {
            int l  = t + i * 256;        // 0..1023
            int m  = l >> 2;             // 0..255
            int kq = l & 3;
            float4 vv = *(const float4*)(A + (long long)(row0 + m) * lda + k0 + kq * 4);
            As[kq*4+0][m] = vv.x; As[kq*4+1][m] = vv.y;
            As[kq*4+2][m] = vv.z; As[kq*4+3][m] = vv.w;
        }
        // B tile 16x64 direct (1 float4 per thread)
        {
            int k  = t >> 4;
            int n4 = t & 15;
            float4 vv = *(const float4*)(B + (long long)(k0 + k) * ldb + col0 + n4 * 4);
            *(float4*)&Bs[k][n4*4] = vv;
        }
        __syncthreads();

        #pragma unroll
        for (int k = 0; k < 16; k++) {
            float a[16], b[4];
            *(float4*)(a)    = *(float4*)&As[k][ty*16];
            *(float4*)(a+4)  = *(float4*)&As[k][ty*16+4];
            *(float4*)(a+8)  = *(float4*)&As[k][ty*16+8];
            *(float4*)(a+12) = *(float4*)&As[k][ty*16+12];
            *(float4*)(b)    = *(float4*)&Bs[k][tx*4];
            #pragma unroll
            for (int i = 0; i < 16; i++)
                #pragma unroll
                for (int j = 0; j < 4; j++)
                    acc[i][j] = fmaf(a[i], b[j], acc[i][j]);
        }
        __syncthreads();
    }

    #pragma unroll
    for (int i = 0; i < 16; i++) {
        int row = row0 + ty * 16 + i;
        #pragma unroll
        for (int j = 0; j < 4; j++) {
            int col = col0 + tx * 4 + j;
            C[(long long)row * ldc + col] = acc[i][j];
        }
    }
}

// ---------------------------------------------------------------------------
// Row softmax over S=1024 with optional causal mask.
// One block (256 threads) per row; row index = bh*S + q.
// ---------------------------------------------------------------------------
__global__ void __launch_bounds__(256) softmax_rows(float* __restrict__ Sc, int causal)
{
    __shared__ float red[8];
    long long row = blockIdx.x;
    int q = (int)(row & (SS - 1));
    float* r = Sc + row * SS;
    int t = threadIdx.x;

    float4 v = *(float4*)(r + t * 4);
    if (causal) {
        int k = t * 4;
        if (k + 0 > q) v.x = -1e30f;
        if (k + 1 > q) v.y = -1e30f;
        if (k + 2 > q) v.z = -1e30f;
        if (k + 3 > q) v.w = -1e30f;
    }
    float m = fmaxf(fmaxf(v.x, v.y), fmaxf(v.z, v.w));
    #pragma unroll
    for (int o = 16; o > 0; o >>= 1) m = fmaxf(m, __shfl_xor_sync(0xffffffffu, m, o));
    if ((t & 31) == 0) red[t >> 5] = m;
    __syncthreads();
    m = red[0];
    #pragma unroll
    for (int i = 1; i < 8; i++) m = fmaxf(m, red[i]);
    __syncthreads();

    float4 e;
    e.x = __expf(v.x - m); e.y = __expf(v.y - m);
    e.z = __expf(v.z - m); e.w = __expf(v.w - m);
    float s = e.x + e.y + e.z + e.w;
    #pragma unroll
    for (int o = 16; o > 0; o >>= 1) s += __shfl_xor_sync(0xffffffffu, s, o);
    if ((t & 31) == 0) red[t >> 5] = s;
    __syncthreads();
    s = red[0];
    #pragma unroll
    for (int i = 1; i < 8; i++) s += red[i];

    float inv = 1.0f / s;
    e.x *= inv; e.y *= inv; e.z *= inv; e.w *= inv;
    *(float4*)(r + t * 4) = e;
}

// ---------------------------------------------------------------------------
// out = LayerNorm(a + b) * g + beta      (rows of D=1024, 256 thr/row)
// ---------------------------------------------------------------------------
__global__ void __launch_bounds__(256) add_ln_kernel(
    const float* __restrict__ A, const float* __restrict__ Bv,
    const float* __restrict__ g, const float* __restrict__ be,
    float* __restrict__ out)
{
    __shared__ float redS[8];
    __shared__ float redQ[8];
    long long row = blockIdx.x;
    int t = threadIdx.x;

    float4 a = *(const float4*)(A  + row * DD + t * 4);
    float4 b = *(const float4*)(Bv + row * DD + t * 4);
    float4 s;
    s.x = a.x + b.x; s.y = a.y + b.y; s.z = a.z + b.z; s.w = a.w + b.w;

    float sum = s.x + s.y + s.z + s.w;
    float sq  = s.x*s.x + s.y*s.y + s.z*s.z + s.w*s.w;
    #pragma unroll
    for (int o = 16; o > 0; o >>= 1) {
        sum += __shfl_xor_sync(0xffffffffu, sum, o);
        sq  += __shfl_xor_sync(0xffffffffu, sq,  o);
    }
    if ((t & 31) == 0) { redS[t >> 5] = sum; redQ[t >> 5] = sq; }
    __syncthreads();
    sum = 0.f; sq = 0.f;
    #pragma unroll
    for (int i = 0; i < 8; i++) { sum += redS[i]; sq += redQ[i]; }

    float mean = sum * (1.0f / DD);
    float var  = sq  * (1.0f / DD) - mean * mean;
    float rstd = rsqrtf(var + 1e-5f);

    float4 gg = *(const float4*)(g  + t * 4);
    float4 bb = *(const float4*)(be + t * 4);
    float4 o;
    o.x = (s.x - mean) * rstd * gg.x + bb.x;
    o.y = (s.y - mean) * rstd * gg.y + bb.y;
    o.z = (s.z - mean) * rstd * gg.z + bb.z;
    o.w = (s.w - mean) * rstd * gg.w + bb.w;
    *(float4*)(out + row * DD + t * 4) = o;
}

// ---------------------------------------------------------------------------
// Launch
// ---------------------------------------------------------------------------
extern "C" void kernel_launch(void* const* d_in, const int* in_sizes, int n_in,
                              void* d_out, int out_size)
{
    const float* x        = (const float*)d_in[0];
    const float* enc      = (const float*)d_in[1];
    // d_in[2]=source_mask (unused by ref attn), d_in[3]=target_mask (tril -> hardcoded causal)
    const float* sa_wq    = (const float*)d_in[4];
    const float* sa_bq    = (const float*)d_in[5];
    const float* sa_wk    = (const float*)d_in[6];
    const float* sa_bk    = (const float*)d_in[7];
    const float* sa_wv    = (const float*)d_in[8];
    const float* sa_bv    = (const float*)d_in[9];
    const float* sa_wo    = (const float*)d_in[10];
    const float* sa_bo    = (const float*)d_in[11];
    const float* ca_in_w  = (const float*)d_in[12];
    const float* ca_in_b  = (const float*)d_in[13];
    const float* ca_out_w = (const float*)d_in[14];
    const float* ca_out_b = (const float*)d_in[15];
    const float* ff_w1    = (const float*)d_in[16];
    const float* ff_b1    = (const float*)d_in[17];
    const float* ff_w2    = (const float*)d_in[18];
    const float* ff_b2    = (const float*)d_in[19];
    const float* n1_g     = (const float*)d_in[20];
    const float* n1_b     = (const float*)d_in[21];
    const float* n2_g     = (const float*)d_in[22];
    const float* n2_b     = (const float*)d_in[23];
    const float* n3_g     = (const float*)d_in[24];
    const float* n3_b     = (const float*)d_in[25];
    float* out = (float*)d_out;

    float *q, *k, *v, *attn, *tmp, *x1, *x2, *sc, *hid;
    cudaGetSymbolAddress((void**)&q,    g_q);
    cudaGetSymbolAddress((void**)&k,    g_k);
    cudaGetSymbolAddress((void**)&v,    g_v);
    cudaGetSymbolAddress((void**)&attn, g_attn);
    cudaGetSymbolAddress((void**)&tmp,  g_tmp);
    cudaGetSymbolAddress((void**)&x1,   g_x1);
    cudaGetSymbolAddress((void**)&x2,   g_x2);
    cudaGetSymbolAddress((void**)&sc,   g_scores);
    cudaGetSymbolAddress((void**)&hid,  g_hidden);

    const float scale = 0.125f;  // 1/sqrt(64)
    dim3 blk(256);
    dim3 gProj(DD/128, MM/128, 1);                 // token-major projections
    dim3 gScore(SS/128, SS/128, BH);               // batched QK^T
    dim3 gPV(1, SS/256, BH);                       // batched P@V
    dim3 gFF1(DFFN/128, MM/128, 1);
    long long SD = (long long)SS * DD;             // batch stride of activations
    long long SSq = (long long)SS * SS;            // per-head score stride

    // ---- Self-attention ----
    gemm_tn<false><<<gProj, blk>>>(x, DD,0,0, sa_wq, DD,0,0, sa_bq, q, DD,0,0, MM,DD,DD, 1.f, 1);
    gemm_tn<false><<<gProj, blk>>>(x, DD,0,0, sa_wk, DD,0,0, sa_bk, k, DD,0,0, MM,DD,DD, 1.f, 1);
    gemm_tn<false><<<gProj, blk>>>(x, DD,0,0, sa_wv, DD,0,0, sa_bv, v, DD,0,0, MM,DD,DD, 1.f, 1);
    gemm_tn<false><<<gScore, blk>>>(q, DD, SD, DKK, k, DD, SD, DKK, nullptr,
                                    sc, SS, (long long)HH*SSq, SSq, SS,SS,DKK, scale, HH);
    softmax_rows<<<BH*SS, blk>>>(sc, 1);
    gemm_nn<<<gPV, blk>>>(sc, SS, (long long)HH*SSq, SSq, v, DD, SD, DKK,
                          attn, DD, SD, DKK, SS, DKK, SS, HH);
    gemm_tn<false><<<gProj, blk>>>(attn, DD,0,0, sa_wo, DD,0,0, sa_bo, tmp, DD,0,0, MM,DD,DD, 1.f, 1);
    add_ln_kernel<<<MM, blk>>>(x, tmp, n1_g, n1_b, x1);

    // ---- Cross-attention ----
    gemm_tn<false><<<gProj, blk>>>(x1,  DD,0,0, ca_in_w,              DD,0,0, ca_in_b,        q, DD,0,0, MM,DD,DD, 1.f, 1);
    gemm_tn<false><<<gProj, blk>>>(enc, DD,0,0, ca_in_w + (long long)DD*DD,   DD,0,0, ca_in_b + DD,   k, DD,0,0, MM,DD,DD, 1.f, 1);
    gemm_tn<false><<<gProj, blk>>>(enc, DD,0,0, ca_in_w + 2ll*DD*DD,  DD,0,0, ca_in_b + 2*DD, v, DD,0,0, MM,DD,DD, 1.f, 1);
    gemm_tn<false><<<gScore, blk>>>(q, DD, SD, DKK, k, DD, SD, DKK, nullptr,
                                    sc, SS, (long long)HH*SSq, SSq, SS,SS,DKK, scale, HH);
    softmax_rows<<<BH*SS, blk>>>(sc, 0);
    gemm_nn<<<gPV, blk>>>(sc, SS, (long long)HH*SSq, SSq, v, DD, SD, DKK,
                          attn, DD, SD, DKK, SS, DKK, SS, HH);
    gemm_tn<false><<<gProj, blk>>>(attn, DD,0,0, ca_out_w, DD,0,0, ca_out_b, tmp, DD,0,0, MM,DD,DD, 1.f, 1);
    add_ln_kernel<<<MM, blk>>>(x1, tmp, n2_g, n2_b, x2);

    // ---- FFN ----
    gemm_tn<true ><<<gFF1,  blk>>>(x2,  DFFN==DFFN?DD:DD,0,0, ff_w1, DD,0,0,   ff_b1, hid, DFFN,0,0, MM,DFFN,DD,  1.f, 1);
    gemm_tn<false><<<gProj, blk>>>(hid, DFFN,0,0,             ff_w2, DFFN,0,0, ff_b2, tmp, DD,0,0,   MM,DD,DFFN,  1.f, 1);
    add_ln_kernel<<<MM, blk>>>(x2, tmp, n3_g, n3_b, out);
}

// round 3
// speedup vs baseline: 2.8221x; 2.8221x over previous
#include <cuda_runtime.h>
#include <cuda_bf16.h>
#include <cstdint>
#include <math.h>

// Problem constants
#define BB   4
#define SS   1024
#define DD   1024
#define HH   16
#define DKK  64
#define DFFN 4096
#define MM   (BB*SS)        // 4096 token rows
#define BH   (BB*HH)        // 64

// ---------------------------------------------------------------------------
// Scratch (device globals: allocation inside kernel_launch is forbidden)
// ---------------------------------------------------------------------------
__device__ float g_q[MM*DD];
__device__ float g_k[MM*DD];
__device__ float g_v[MM*DD];
__device__ float g_attn[MM*DD];
__device__ float g_tmp[MM*DD];
__device__ float g_x1[MM*DD];
__device__ float g_x2[MM*DD];
__device__ float g_scores[(long long)BH*SS*SS];   // 268MB
__device__ float g_hidden[(long long)MM*DFFN];    // 67MB

// ---------------------------------------------------------------------------
// tf32 helpers
// ---------------------------------------------------------------------------
__device__ __forceinline__ unsigned int f2tf32(float f) {
    unsigned int r;
    asm("cvt.rna.tf32.f32 %0, %1;" : "=r"(r) : "f"(f));
    return r;
}

__device__ __forceinline__ void mma_tf32(float (&c)[4],
                                         const unsigned int (&a)[4],
                                         const unsigned int (&b)[2]) {
    asm volatile(
        "mma.sync.aligned.m16n8k8.row.col.f32.tf32.tf32.f32 "
        "{%0,%1,%2,%3}, {%4,%5,%6,%7}, {%8,%9}, {%0,%1,%2,%3};"
        : "+f"(c[0]), "+f"(c[1]), "+f"(c[2]), "+f"(c[3])
        : "r"(a[0]), "r"(a[1]), "r"(a[2]), "r"(a[3]),
          "r"(b[0]), "r"(b[1]));
}

// ---------------------------------------------------------------------------
// Tensor-core GEMM (tf32 mma.sync).
//   C = alpha * (A  @  op(B)) + bias [, relu]
//   A: [M,K] row-major, lda.
//   WB_TRANS=true : B is weights [N,K] row-major (C = A @ B^T)
//   WB_TRANS=false: B is [K,N] row-major        (C = A @ B)
// Batched via blockIdx.z: off = (z/zdiv)*s1 + (z%zdiv)*s2.
// BK=32. 8 warps (256 threads). Warp tile WM x WN, m16n8k8 fragments.
// SMEM: As[BM][36] (m-major), Bs[BN][36] (n-major) -> conflict-free frag loads.
// ---------------------------------------------------------------------------
template<int BM, int BN, int WM, int WN, bool WB_TRANS, bool RELU>
__global__ void __launch_bounds__(256, 2) mma_gemm(
    const float* __restrict__ A, int lda, long long sA1, long long sA2,
    const float* __restrict__ B, int ldb, long long sB1, long long sB2,
    const float* __restrict__ bias,
    float* __restrict__ C, int ldc, long long sC1, long long sC2,
    int K, float alpha, int zdiv)
{
    constexpr int MT = WM / 16;
    constexpr int NT = WN / 8;
    constexpr int NWN = BN / WN;          // warps along N

    __shared__ unsigned int As[BM][36];
    __shared__ unsigned int Bs[BN][36];

    int z  = blockIdx.z;
    int zb = z / zdiv, zh = z % zdiv;
    A += zb * sA1 + zh * sA2;
    B += zb * sB1 + zh * sB2;
    C += zb * sC1 + zh * sC2;

    const int row0 = blockIdx.y * BM;
    const int col0 = blockIdx.x * BN;
    const int t    = threadIdx.x;
    const int w    = t >> 5;
    const int lane = t & 31;
    const int wm   = w / NWN;
    const int wn   = w % NWN;
    const int gr   = lane >> 2;   // groupID (0..7)
    const int gc   = lane & 3;    // thread-in-group (0..3)

    float acc[MT][NT][4];
    #pragma unroll
    for (int i = 0; i < MT; i++)
        #pragma unroll
        for (int j = 0; j < NT; j++)
            #pragma unroll
            for (int r = 0; r < 4; r++) acc[i][j][r] = 0.f;

    for (int k0 = 0; k0 < K; k0 += 32) {
        // ---- Load A tile [BM x 32] -> As[m][k], tf32-converted ----
        #pragma unroll
        for (int i = 0; i < BM / 32; i++) {
            int l  = t + i * 256;
            int m  = l >> 3;          // row in tile
            int kq = l & 7;           // float4 index in k
            float4 v = *(const float4*)(A + (long long)(row0 + m) * lda + k0 + kq * 4);
            As[m][kq * 4 + 0] = f2tf32(v.x);
            As[m][kq * 4 + 1] = f2tf32(v.y);
            As[m][kq * 4 + 2] = f2tf32(v.z);
            As[m][kq * 4 + 3] = f2tf32(v.w);
        }
        // ---- Load B tile -> Bs[n][k] ----
        if (WB_TRANS) {
            // B [N,K] row-major: coalesced float4 copy along K
            #pragma unroll
            for (int i = 0; i < BN / 32; i++) {
                int l  = t + i * 256;
                int n  = l >> 3;
                int kq = l & 7;
                float4 v = *(const float4*)(B + (long long)(col0 + n) * ldb + k0 + kq * 4);
                Bs[n][kq * 4 + 0] = f2tf32(v.x);
                Bs[n][kq * 4 + 1] = f2tf32(v.y);
                Bs[n][kq * 4 + 2] = f2tf32(v.z);
                Bs[n][kq * 4 + 3] = f2tf32(v.w);
            }
        } else {
            // B [K,N] row-major: float4 along N, transposed scatter into Bs
            constexpr int F4 = BN / 4;
            #pragma unroll
            for (int i = 0; i < BN / 32; i++) {
                int l  = t + i * 256;
                int k  = l / F4;
                int nq = l % F4;
                float4 v = *(const float4*)(B + (long long)(k0 + k) * ldb + col0 + nq * 4);
                Bs[nq * 4 + 0][k] = f2tf32(v.x);
                Bs[nq * 4 + 1][k] = f2tf32(v.y);
                Bs[nq * 4 + 2][k] = f2tf32(v.z);
                Bs[nq * 4 + 3][k] = f2tf32(v.w);
            }
        }
        __syncthreads();

        // ---- Compute: 4 k-steps of m16n8k8 ----
        #pragma unroll
        for (int ks = 0; ks < 32; ks += 8) {
            unsigned int af[MT][4];
            unsigned int bf[NT][2];
            #pragma unroll
            for (int mt = 0; mt < MT; mt++) {
                int r = wm * WM + mt * 16 + gr;
                af[mt][0] = As[r    ][ks + gc];
                af[mt][1] = As[r + 8][ks + gc];
                af[mt][2] = As[r    ][ks + gc + 4];
                af[mt][3] = As[r + 8][ks + gc + 4];
            }
            #pragma unroll
            for (int nt = 0; nt < NT; nt++) {
                int n = wn * WN + nt * 8 + gr;
                bf[nt][0] = Bs[n][ks + gc];
                bf[nt][1] = Bs[n][ks + gc + 4];
            }
            #pragma unroll
            for (int mt = 0; mt < MT; mt++)
                #pragma unroll
                for (int nt = 0; nt < NT; nt++)
                    mma_tf32(acc[mt][nt], af[mt], bf[nt]);
        }
        __syncthreads();
    }

    // ---- Epilogue ----
    #pragma unroll
    for (int mt = 0; mt < MT; mt++) {
        #pragma unroll
        for (int nt = 0; nt < NT; nt++) {
            int row = row0 + wm * WM + mt * 16 + gr;
            int col = col0 + wn * WN + nt * 8 + gc * 2;
            float b0 = 0.f, b1 = 0.f;
            if (bias) { b0 = bias[col]; b1 = bias[col + 1]; }
            float v0 = acc[mt][nt][0] * alpha + b0;
            float v1 = acc[mt][nt][1] * alpha + b1;
            float v2 = acc[mt][nt][2] * alpha + b0;
            float v3 = acc[mt][nt][3] * alpha + b1;
            if (RELU) {
                v0 = fmaxf(v0, 0.f); v1 = fmaxf(v1, 0.f);
                v2 = fmaxf(v2, 0.f); v3 = fmaxf(v3, 0.f);
            }
            *(float2*)(C + (long long)row * ldc + col)       = make_float2(v0, v1);
            *(float2*)(C + (long long)(row + 8) * ldc + col) = make_float2(v2, v3);
        }
    }
}

// ---------------------------------------------------------------------------
// Row softmax over S=1024 with optional causal mask.
// ---------------------------------------------------------------------------
__global__ void __launch_bounds__(256) softmax_rows(float* __restrict__ Sc, int causal)
{
    __shared__ float red[8];
    long long row = blockIdx.x;
    int q = (int)(row & (SS - 1));
    float* r = Sc + row * SS;
    int t = threadIdx.x;

    float4 v = *(float4*)(r + t * 4);
    if (causal) {
        int k = t * 4;
        if (k + 0 > q) v.x = -1e30f;
        if (k + 1 > q) v.y = -1e30f;
        if (k + 2 > q) v.z = -1e30f;
        if (k + 3 > q) v.w = -1e30f;
    }
    float m = fmaxf(fmaxf(v.x, v.y), fmaxf(v.z, v.w));
    #pragma unroll
    for (int o = 16; o > 0; o >>= 1) m = fmaxf(m, __shfl_xor_sync(0xffffffffu, m, o));
    if ((t & 31) == 0) red[t >> 5] = m;
    __syncthreads();
    m = red[0];
    #pragma unroll
    for (int i = 1; i < 8; i++) m = fmaxf(m, red[i]);
    __syncthreads();

    float4 e;
    e.x = __expf(v.x - m); e.y = __expf(v.y - m);
    e.z = __expf(v.z - m); e.w = __expf(v.w - m);
    float s = e.x + e.y + e.z + e.w;
    #pragma unroll
    for (int o = 16; o > 0; o >>= 1) s += __shfl_xor_sync(0xffffffffu, s, o);
    if ((t & 31) == 0) red[t >> 5] = s;
    __syncthreads();
    s = red[0];
    #pragma unroll
    for (int i = 1; i < 8; i++) s += red[i];

    float inv = 1.0f / s;
    e.x *= inv; e.y *= inv; e.z *= inv; e.w *= inv;
    *(float4*)(r + t * 4) = e;
}

// ---------------------------------------------------------------------------
// out = LayerNorm(a + b) * g + beta
// ---------------------------------------------------------------------------
__global__ void __launch_bounds__(256) add_ln_kernel(
    const float* __restrict__ A, const float* __restrict__ Bv,
    const float* __restrict__ g, const float* __restrict__ be,
    float* __restrict__ out)
{
    __shared__ float redS[8];
    __shared__ float redQ[8];
    long long row = blockIdx.x;
    int t = threadIdx.x;

    float4 a = *(const float4*)(A  + row * DD + t * 4);
    float4 b = *(const float4*)(Bv + row * DD + t * 4);
    float4 s;
    s.x = a.x + b.x; s.y = a.y + b.y; s.z = a.z + b.z; s.w = a.w + b.w;

    float sum = s.x + s.y + s.z + s.w;
    float sq  = s.x*s.x + s.y*s.y + s.z*s.z + s.w*s.w;
    #pragma unroll
    for (int o = 16; o > 0; o >>= 1) {
        sum += __shfl_xor_sync(0xffffffffu, sum, o);
        sq  += __shfl_xor_sync(0xffffffffu, sq,  o);
    }
    if ((t & 31) == 0) { redS[t >> 5] = sum; redQ[t >> 5] = sq; }
    __syncthreads();
    sum = 0.f; sq = 0.f;
    #pragma unroll
    for (int i = 0; i < 8; i++) { sum += redS[i]; sq += redQ[i]; }

    float mean = sum * (1.0f / DD);
    float var  = sq  * (1.0f / DD) - mean * mean;
    float rstd = rsqrtf(var + 1e-5f);

    float4 gg = *(const float4*)(g  + t * 4);
    float4 bb = *(const float4*)(be + t * 4);
    float4 o;
    o.x = (s.x - mean) * rstd * gg.x + bb.x;
    o.y = (s.y - mean) * rstd * gg.y + bb.y;
    o.z = (s.z - mean) * rstd * gg.z + bb.z;
    o.w = (s.w - mean) * rstd * gg.w + bb.w;
    *(float4*)(out + row * DD + t * 4) = o;
}

// ---------------------------------------------------------------------------
// Launch
// ---------------------------------------------------------------------------
extern "C" void kernel_launch(void* const* d_in, const int* in_sizes, int n_in,
                              void* d_out, int out_size)
{
    const float* x        = (const float*)d_in[0];
    const float* enc      = (const float*)d_in[1];
    const float* sa_wq    = (const float*)d_in[4];
    const float* sa_bq    = (const float*)d_in[5];
    const float* sa_wk    = (const float*)d_in[6];
    const float* sa_bk    = (const float*)d_in[7];
    const float* sa_wv    = (const float*)d_in[8];
    const float* sa_bv    = (const float*)d_in[9];
    const float* sa_wo    = (const float*)d_in[10];
    const float* sa_bo    = (const float*)d_in[11];
    const float* ca_in_w  = (const float*)d_in[12];
    const float* ca_in_b  = (const float*)d_in[13];
    const float* ca_out_w = (const float*)d_in[14];
    const float* ca_out_b = (const float*)d_in[15];
    const float* ff_w1    = (const float*)d_in[16];
    const float* ff_b1    = (const float*)d_in[17];
    const float* ff_w2    = (const float*)d_in[18];
    const float* ff_b2    = (const float*)d_in[19];
    const float* n1_g     = (const float*)d_in[20];
    const float* n1_b     = (const float*)d_in[21];
    const float* n2_g     = (const float*)d_in[22];
    const float* n2_b     = (const float*)d_in[23];
    const float* n3_g     = (const float*)d_in[24];
    const float* n3_b     = (const float*)d_in[25];
    float* out = (float*)d_out;

    float *q, *k, *v, *attn, *tmp, *x1, *x2, *sc, *hid;
    cudaGetSymbolAddress((void**)&q,    g_q);
    cudaGetSymbolAddress((void**)&k,    g_k);
    cudaGetSymbolAddress((void**)&v,    g_v);
    cudaGetSymbolAddress((void**)&attn, g_attn);
    cudaGetSymbolAddress((void**)&tmp,  g_tmp);
    cudaGetSymbolAddress((void**)&x1,   g_x1);
    cudaGetSymbolAddress((void**)&x2,   g_x2);
    cudaGetSymbolAddress((void**)&sc,   g_scores);
    cudaGetSymbolAddress((void**)&hid,  g_hidden);

    const float scale = 0.125f;  // 1/sqrt(64)
    dim3 blk(256);
    dim3 gProj(DD/128, MM/128, 1);
    dim3 gScore(SS/128, SS/128, BH);
    dim3 gPV(1, SS/128, BH);
    dim3 gFF1(DFFN/128, MM/128, 1);
    long long SD  = (long long)SS * DD;
    long long SSq = (long long)SS * SS;

    // ---- Self-attention ----
    mma_gemm<128,128,64,32,true,false><<<gProj, blk>>>(x, DD,0,0, sa_wq, DD,0,0, sa_bq, q, DD,0,0, DD, 1.f, 1);
    mma_gemm<128,128,64,32,true,false><<<gProj, blk>>>(x, DD,0,0, sa_wk, DD,0,0, sa_bk, k, DD,0,0, DD, 1.f, 1);
    mma_gemm<128,128,64,32,true,false><<<gProj, blk>>>(x, DD,0,0, sa_wv, DD,0,0, sa_bv, v, DD,0,0, DD, 1.f, 1);
    mma_gemm<128,128,64,32,true,false><<<gScore, blk>>>(q, DD, SD, DKK, k, DD, SD, DKK, (const float*)0,
                                  sc, SS, (long long)HH*SSq, SSq, DKK, scale, HH);
    softmax_rows<<<BH*SS, blk>>>(sc, 1);
    mma_gemm<128,64,32,32,false,false><<<gPV, blk>>>(sc, SS, (long long)HH*SSq, SSq, v, DD, SD, DKK, (const float*)0,
                      attn, DD, SD, DKK, SS, 1.f, HH);
    mma_gemm<128,128,64,32,true,false><<<gProj, blk>>>(attn, DD,0,0, sa_wo, DD,0,0, sa_bo, tmp, DD,0,0, DD, 1.f, 1);
    add_ln_kernel<<<MM, blk>>>(x, tmp, n1_g, n1_b, x1);

    // ---- Cross-attention ----
    mma_gemm<128,128,64,32,true,false><<<gProj, blk>>>(x1,  DD,0,0, ca_in_w,             DD,0,0, ca_in_b,        q, DD,0,0, DD, 1.f, 1);
    mma_gemm<128,128,64,32,true,false><<<gProj, blk>>>(enc, DD,0,0, ca_in_w + (long long)DD*DD,  DD,0,0, ca_in_b + DD,   k, DD,0,0, DD, 1.f, 1);
    mma_gemm<128,128,64,32,true,false><<<gProj, blk>>>(enc, DD,0,0, ca_in_w + 2ll*DD*DD, DD,0,0, ca_in_b + 2*DD, v, DD,0,0, DD, 1.f, 1);
    mma_gemm<128,128,64,32,true,false><<<gScore, blk>>>(q, DD, SD, DKK, k, DD, SD, DKK, (const float*)0,
                                  sc, SS, (long long)HH*SSq, SSq, DKK, scale, HH);
    softmax_rows<<<BH*SS, blk>>>(sc, 0);
    mma_gemm<128,64,32,32,false,false><<<gPV, blk>>>(sc, SS, (long long)HH*SSq, SSq, v, DD, SD, DKK, (const float*)0,
                      attn, DD, SD, DKK, SS, 1.f, HH);
    mma_gemm<128,128,64,32,true,false><<<gProj, blk>>>(attn, DD,0,0, ca_out_w, DD,0,0, ca_out_b, tmp, DD,0,0, DD, 1.f, 1);
    add_ln_kernel<<<MM, blk>>>(x1, tmp, n2_g, n2_b, x2);

    // ---- FFN ----
    mma_gemm<128,128,64,32,true,true ><<<gFF1,  blk>>>(x2,  DD,0,0,   ff_w1, DD,0,0,   ff_b1, hid, DFFN,0,0, DD,   1.f, 1);
    mma_gemm<128,128,64,32,true,false><<<gProj, blk>>>(hid, DFFN,0,0, ff_w2, DFFN,0,0, ff_b2, tmp, DD,0,0,   DFFN, 1.f, 1);
    add_ln_kernel<<<MM, blk>>>(x2, tmp, n3_g, n3_b, out);
}

// round 5
// speedup vs baseline: 3.1423x; 1.1135x over previous
#include <cuda_runtime.h>
#include <cuda_bf16.h>
#include <cstdint>
#include <math.h>

// Problem constants
#define BB   4
#define SS   1024
#define DD   1024
#define HH   16
#define DKK  64
#define DFFN 4096
#define MM   (BB*SS)        // 4096 token rows
#define BH   (BB*HH)        // 64

// ---------------------------------------------------------------------------
// Scratch
// ---------------------------------------------------------------------------
__device__ float g_q[MM*DD];
__device__ float g_k[MM*DD];
__device__ float g_v[MM*DD];
__device__ float g_attn[MM*DD];
__device__ float g_tmp[MM*DD];
__device__ float g_x1[MM*DD];
__device__ float g_x2[MM*DD];
__device__ float g_scores[(long long)BH*SS*SS];   // 268MB
__device__ float g_hidden[(long long)MM*DFFN];    // 67MB

// ---------------------------------------------------------------------------
// helpers
// ---------------------------------------------------------------------------
__device__ __forceinline__ void mma_tf32(float (&c)[4],
                                         const unsigned int (&a)[4],
                                         const unsigned int (&b)[2]) {
    asm volatile(
        "mma.sync.aligned.m16n8k8.row.col.f32.tf32.tf32.f32 "
        "{%0,%1,%2,%3}, {%4,%5,%6,%7}, {%8,%9}, {%0,%1,%2,%3};"
        : "+f"(c[0]), "+f"(c[1]), "+f"(c[2]), "+f"(c[3])
        : "r"(a[0]), "r"(a[1]), "r"(a[2]), "r"(a[3]),
          "r"(b[0]), "r"(b[1]));
}

__device__ __forceinline__ void cp16(unsigned int saddr, const float* g) {
    asm volatile("cp.async.cg.shared.global [%0], [%1], 16;\n" :: "r"(saddr), "l"(g));
}
__device__ __forceinline__ void cp_commit() {
    asm volatile("cp.async.commit_group;\n" ::);
}
__device__ __forceinline__ void cp_wait1() {
    asm volatile("cp.async.wait_group 1;\n" ::);
}
__device__ __forceinline__ void cp_wait0() {
    asm volatile("cp.async.wait_group 0;\n" ::);
}

// ---------------------------------------------------------------------------
// Async double-buffered tf32 tensor-core GEMM (TN):
//   C = alpha * (A @ B^T) + bias [, relu]
//   A: [M,K] row-major (lda), B: [N,K] row-major (ldb) -- both f32.
// f32 bits fed directly as tf32 (hardware ignores low mantissa bits).
// BK=32, 2-stage cp.async pipeline in DYNAMIC shared memory (73728 B).
// 8 warps, warp tile WM x WN. Row stride 36 -> conflict-free frag loads.
// ---------------------------------------------------------------------------
template<int BM, int BN, int WM, int WN, bool RELU>
__global__ void __launch_bounds__(256, 2) gemm_tc(
    const float* __restrict__ A, int lda, long long sA1, long long sA2,
    const float* __restrict__ B, int ldb, long long sB1, long long sB2,
    const float* __restrict__ bias,
    float* __restrict__ C, int ldc, long long sC1, long long sC2,
    int K, float alpha, int zdiv)
{
    constexpr int MT  = WM / 16;
    constexpr int NT  = WN / 8;
    constexpr int NWN = BN / WN;

    extern __shared__ float smem[];
    // layout: As[2][BM][36] then Bs[2][BN][36]
    float* AsBase = smem;
    float* BsBase = smem + 2 * BM * 36;

    int z  = blockIdx.z;
    int zb = z / zdiv, zh = z % zdiv;
    A += zb * sA1 + zh * sA2;
    B += zb * sB1 + zh * sB2;
    C += zb * sC1 + zh * sC2;

    const int row0 = blockIdx.y * BM;
    const int col0 = blockIdx.x * BN;
    const int t    = threadIdx.x;
    const int w    = t >> 5;
    const int lane = t & 31;
    const int wm   = w / NWN;
    const int wn   = w % NWN;
    const int gr   = lane >> 2;
    const int gc   = lane & 3;

    // Copy descriptors: thread t copies 16B chunks (m0 + 32i, kq)
    const int m0 = t >> 3;          // 0..31
    const int kq = t & 7;           // 0..7 (float4 within the 32-wide k tile)

    const float* gA = A + (long long)(row0 + m0) * lda + kq * 4;
    const float* gB = B + (long long)(col0 + m0) * ldb + kq * 4;

    unsigned int aBase = (unsigned int)__cvta_generic_to_shared(AsBase);
    unsigned int bBase = (unsigned int)__cvta_generic_to_shared(BsBase);
    constexpr unsigned int stageA = BM * 36 * 4;   // bytes per A stage
    constexpr unsigned int stageB = BN * 36 * 4;

    float acc[MT][NT][4];
    #pragma unroll
    for (int i = 0; i < MT; i++)
        #pragma unroll
        for (int j = 0; j < NT; j++)
            #pragma unroll
            for (int r = 0; r < 4; r++) acc[i][j][r] = 0.f;

    const int nk = K >> 5;

    // preload tile 0 into stage 0
    #pragma unroll
    for (int i = 0; i < BM / 32; i++)
        cp16(aBase + ((m0 + 32 * i) * 36 + kq * 4) * 4, gA + (long long)(32 * i) * lda);
    #pragma unroll
    for (int i = 0; i < BN / 32; i++)
        cp16(bBase + ((m0 + 32 * i) * 36 + kq * 4) * 4, gB + (long long)(32 * i) * ldb);
    cp_commit();

    for (int it = 0; it < nk; it++) {
        const int cur = it & 1;
        if (it + 1 < nk) {
            const int nxt = cur ^ 1;
            const float* gA2 = gA + (it + 1) * 32;
            const float* gB2 = gB + (it + 1) * 32;
            #pragma unroll
            for (int i = 0; i < BM / 32; i++)
                cp16(aBase + nxt * stageA + ((m0 + 32 * i) * 36 + kq * 4) * 4,
                     gA2 + (long long)(32 * i) * lda);
            #pragma unroll
            for (int i = 0; i < BN / 32; i++)
                cp16(bBase + nxt * stageB + ((m0 + 32 * i) * 36 + kq * 4) * 4,
                     gB2 + (long long)(32 * i) * ldb);
            cp_commit();
            cp_wait1();
        } else {
            cp_wait0();
        }
        __syncthreads();

        const float* Acur = AsBase + cur * (BM * 36);
        const float* Bcur = BsBase + cur * (BN * 36);

        #pragma unroll
        for (int ks = 0; ks < 32; ks += 8) {
            unsigned int af[MT][4];
            unsigned int bf[NT][2];
            #pragma unroll
            for (int mt = 0; mt < MT; mt++) {
                int r = wm * WM + mt * 16 + gr;
                af[mt][0] = __float_as_uint(Acur[(r    ) * 36 + ks + gc]);
                af[mt][1] = __float_as_uint(Acur[(r + 8) * 36 + ks + gc]);
                af[mt][2] = __float_as_uint(Acur[(r    ) * 36 + ks + gc + 4]);
                af[mt][3] = __float_as_uint(Acur[(r + 8) * 36 + ks + gc + 4]);
            }
            #pragma unroll
            for (int nt = 0; nt < NT; nt++) {
                int n = wn * WN + nt * 8 + gr;
                bf[nt][0] = __float_as_uint(Bcur[n * 36 + ks + gc]);
                bf[nt][1] = __float_as_uint(Bcur[n * 36 + ks + gc + 4]);
            }
            #pragma unroll
            for (int mt = 0; mt < MT; mt++)
                #pragma unroll
                for (int nt = 0; nt < NT; nt++)
                    mma_tf32(acc[mt][nt], af[mt], bf[nt]);
        }
        __syncthreads();
    }

    // ---- Epilogue ----
    #pragma unroll
    for (int mt = 0; mt < MT; mt++) {
        #pragma unroll
        for (int nt = 0; nt < NT; nt++) {
            int row = row0 + wm * WM + mt * 16 + gr;
            int col = col0 + wn * WN + nt * 8 + gc * 2;
            float b0 = 0.f, b1 = 0.f;
            if (bias) { b0 = bias[col]; b1 = bias[col + 1]; }
            float v0 = acc[mt][nt][0] * alpha + b0;
            float v1 = acc[mt][nt][1] * alpha + b1;
            float v2 = acc[mt][nt][2] * alpha + b0;
            float v3 = acc[mt][nt][3] * alpha + b1;
            if (RELU) {
                v0 = fmaxf(v0, 0.f); v1 = fmaxf(v1, 0.f);
                v2 = fmaxf(v2, 0.f); v3 = fmaxf(v3, 0.f);
            }
            *(float2*)(C + (long long)row * ldc + col)       = make_float2(v0, v1);
            *(float2*)(C + (long long)(row + 8) * ldc + col) = make_float2(v2, v3);
        }
    }
}

// ---------------------------------------------------------------------------
// NN tensor-core GEMM (for P @ V): C = A @ B, synchronous loader.
// A: [M,K] (lda), B: [K,N] (ldb). Static smem (27.6 KB).
// ---------------------------------------------------------------------------
template<int BM, int BN, int WM, int WN>
__global__ void __launch_bounds__(256, 2) gemm_nn_tc(
    const float* __restrict__ A, int lda, long long sA1, long long sA2,
    const float* __restrict__ B, int ldb, long long sB1, long long sB2,
    float* __restrict__ C, int ldc, long long sC1, long long sC2,
    int K, int zdiv)
{
    constexpr int MT  = WM / 16;
    constexpr int NT  = WN / 8;
    constexpr int NWN = BN / WN;

    __shared__ unsigned int As[BM][36];
    __shared__ unsigned int Bs[BN][36];

    int z  = blockIdx.z;
    int zb = z / zdiv, zh = z % zdiv;
    A += zb * sA1 + zh * sA2;
    B += zb * sB1 + zh * sB2;
    C += zb * sC1 + zh * sC2;

    const int row0 = blockIdx.y * BM;
    const int col0 = blockIdx.x * BN;
    const int t    = threadIdx.x;
    const int w    = t >> 5;
    const int lane = t & 31;
    const int wm   = w / NWN;
    const int wn   = w % NWN;
    const int gr   = lane >> 2;
    const int gc   = lane & 3;

    float acc[MT][NT][4];
    #pragma unroll
    for (int i = 0; i < MT; i++)
        #pragma unroll
        for (int j = 0; j < NT; j++)
            #pragma unroll
            for (int r = 0; r < 4; r++) acc[i][j][r] = 0.f;

    for (int k0 = 0; k0 < K; k0 += 32) {
        #pragma unroll
        for (int i = 0; i < BM / 32; i++) {
            int l  = t + i * 256;
            int m  = l >> 3;
            int kq = l & 7;
            float4 v = *(const float4*)(A + (long long)(row0 + m) * lda + k0 + kq * 4);
            As[m][kq * 4 + 0] = __float_as_uint(v.x);
            As[m][kq * 4 + 1] = __float_as_uint(v.y);
            As[m][kq * 4 + 2] = __float_as_uint(v.z);
            As[m][kq * 4 + 3] = __float_as_uint(v.w);
        }
        {
            constexpr int F4 = BN / 4;
            #pragma unroll
            for (int i = 0; i < BN / 32; i++) {
                int l  = t + i * 256;
                int k  = l / F4;
                int nq = l % F4;
                float4 v = *(const float4*)(B + (long long)(k0 + k) * ldb + col0 + nq * 4);
                Bs[nq * 4 + 0][k] = __float_as_uint(v.x);
                Bs[nq * 4 + 1][k] = __float_as_uint(v.y);
                Bs[nq * 4 + 2][k] = __float_as_uint(v.z);
                Bs[nq * 4 + 3][k] = __float_as_uint(v.w);
            }
        }
        __syncthreads();

        #pragma unroll
        for (int ks = 0; ks < 32; ks += 8) {
            unsigned int af[MT][4];
            unsigned int bf[NT][2];
            #pragma unroll
            for (int mt = 0; mt < MT; mt++) {
                int r = wm * WM + mt * 16 + gr;
                af[mt][0] = As[r    ][ks + gc];
                af[mt][1] = As[r + 8][ks + gc];
                af[mt][2] = As[r    ][ks + gc + 4];
                af[mt][3] = As[r + 8][ks + gc + 4];
            }
            #pragma unroll
            for (int nt = 0; nt < NT; nt++) {
                int n = wn * WN + nt * 8 + gr;
                bf[nt][0] = Bs[n][ks + gc];
                bf[nt][1] = Bs[n][ks + gc + 4];
            }
            #pragma unroll
            for (int mt = 0; mt < MT; mt++)
                #pragma unroll
                for (int nt = 0; nt < NT; nt++)
                    mma_tf32(acc[mt][nt], af[mt], bf[nt]);
        }
        __syncthreads();
    }

    #pragma unroll
    for (int mt = 0; mt < MT; mt++) {
        #pragma unroll
        for (int nt = 0; nt < NT; nt++) {
            int row = row0 + wm * WM + mt * 16 + gr;
            int col = col0 + wn * WN + nt * 8 + gc * 2;
            *(float2*)(C + (long long)row * ldc + col) =
                make_float2(acc[mt][nt][0], acc[mt][nt][1]);
            *(float2*)(C + (long long)(row + 8) * ldc + col) =
                make_float2(acc[mt][nt][2], acc[mt][nt][3]);
        }
    }
}

// ---------------------------------------------------------------------------
// Row softmax over S=1024 with optional causal mask.
// ---------------------------------------------------------------------------
__global__ void __launch_bounds__(256) softmax_rows(float* __restrict__ Sc, int causal)
{
    __shared__ float red[8];
    long long row = blockIdx.x;
    int q = (int)(row & (SS - 1));
    float* r = Sc + row * SS;
    int t = threadIdx.x;

    float4 v = *(float4*)(r + t * 4);
    if (causal) {
        int k = t * 4;
        if (k + 0 > q) v.x = -1e30f;
        if (k + 1 > q) v.y = -1e30f;
        if (k + 2 > q) v.z = -1e30f;
        if (k + 3 > q) v.w = -1e30f;
    }
    float m = fmaxf(fmaxf(v.x, v.y), fmaxf(v.z, v.w));
    #pragma unroll
    for (int o = 16; o > 0; o >>= 1) m = fmaxf(m, __shfl_xor_sync(0xffffffffu, m, o));
    if ((t & 31) == 0) red[t >> 5] = m;
    __syncthreads();
    m = red[0];
    #pragma unroll
    for (int i = 1; i < 8; i++) m = fmaxf(m, red[i]);
    __syncthreads();

    float4 e;
    e.x = __expf(v.x - m); e.y = __expf(v.y - m);
    e.z = __expf(v.z - m); e.w = __expf(v.w - m);
    float s = e.x + e.y + e.z + e.w;
    #pragma unroll
    for (int o = 16; o > 0; o >>= 1) s += __shfl_xor_sync(0xffffffffu, s, o);
    if ((t & 31) == 0) red[t >> 5] = s;
    __syncthreads();
    s = red[0];
    #pragma unroll
    for (int i = 1; i < 8; i++) s += red[i];

    float inv = 1.0f / s;
    e.x *= inv; e.y *= inv; e.z *= inv; e.w *= inv;
    *(float4*)(r + t * 4) = e;
}

// ---------------------------------------------------------------------------
// out = LayerNorm(a + b) * g + beta
// ---------------------------------------------------------------------------
__global__ void __launch_bounds__(256) add_ln_kernel(
    const float* __restrict__ A, const float* __restrict__ Bv,
    const float* __restrict__ g, const float* __restrict__ be,
    float* __restrict__ out)
{
    __shared__ float redS[8];
    __shared__ float redQ[8];
    long long row = blockIdx.x;
    int t = threadIdx.x;

    float4 a = *(const float4*)(A  + row * DD + t * 4);
    float4 b = *(const float4*)(Bv + row * DD + t * 4);
    float4 s;
    s.x = a.x + b.x; s.y = a.y + b.y; s.z = a.z + b.z; s.w = a.w + b.w;

    float sum = s.x + s.y + s.z + s.w;
    float sq  = s.x*s.x + s.y*s.y + s.z*s.z + s.w*s.w;
    #pragma unroll
    for (int o = 16; o > 0; o >>= 1) {
        sum += __shfl_xor_sync(0xffffffffu, sum, o);
        sq  += __shfl_xor_sync(0xffffffffu, sq,  o);
    }
    if ((t & 31) == 0) { redS[t >> 5] = sum; redQ[t >> 5] = sq; }
    __syncthreads();
    sum = 0.f; sq = 0.f;
    #pragma unroll
    for (int i = 0; i < 8; i++) { sum += redS[i]; sq += redQ[i]; }

    float mean = sum * (1.0f / DD);
    float var  = sq  * (1.0f / DD) - mean * mean;
    float rstd = rsqrtf(var + 1e-5f);

    float4 gg = *(const float4*)(g  + t * 4);
    float4 bb = *(const float4*)(be + t * 4);
    float4 o;
    o.x = (s.x - mean) * rstd * gg.x + bb.x;
    o.y = (s.y - mean) * rstd * gg.y + bb.y;
    o.z = (s.z - mean) * rstd * gg.z + bb.z;
    o.w = (s.w - mean) * rstd * gg.w + bb.w;
    *(float4*)(out + row * DD + t * 4) = o;
}

// ---------------------------------------------------------------------------
// Launch
// ---------------------------------------------------------------------------
extern "C" void kernel_launch(void* const* d_in, const int* in_sizes, int n_in,
                              void* d_out, int out_size)
{
    const float* x        = (const float*)d_in[0];
    const float* enc      = (const float*)d_in[1];
    const float* sa_wq    = (const float*)d_in[4];
    const float* sa_bq    = (const float*)d_in[5];
    const float* sa_wk    = (const float*)d_in[6];
    const float* sa_bk    = (const float*)d_in[7];
    const float* sa_wv    = (const float*)d_in[8];
    const float* sa_bv    = (const float*)d_in[9];
    const float* sa_wo    = (const float*)d_in[10];
    const float* sa_bo    = (const float*)d_in[11];
    const float* ca_in_w  = (const float*)d_in[12];
    const float* ca_in_b  = (const float*)d_in[13];
    const float* ca_out_w = (const float*)d_in[14];
    const float* ca_out_b = (const float*)d_in[15];
    const float* ff_w1    = (const float*)d_in[16];
    const float* ff_b1    = (const float*)d_in[17];
    const float* ff_w2    = (const float*)d_in[18];
    const float* ff_b2    = (const float*)d_in[19];
    const float* n1_g     = (const float*)d_in[20];
    const float* n1_b     = (const float*)d_in[21];
    const float* n2_g     = (const float*)d_in[22];
    const float* n2_b     = (const float*)d_in[23];
    const float* n3_g     = (const float*)d_in[24];
    const float* n3_b     = (const float*)d_in[25];
    float* out = (float*)d_out;

    float *q, *k, *v, *attn, *tmp, *x1, *x2, *sc, *hid;
    cudaGetSymbolAddress((void**)&q,    g_q);
    cudaGetSymbolAddress((void**)&k,    g_k);
    cudaGetSymbolAddress((void**)&v,    g_v);
    cudaGetSymbolAddress((void**)&attn, g_attn);
    cudaGetSymbolAddress((void**)&tmp,  g_tmp);
    cudaGetSymbolAddress((void**)&x1,   g_x1);
    cudaGetSymbolAddress((void**)&x2,   g_x2);
    cudaGetSymbolAddress((void**)&sc,   g_scores);
    cudaGetSymbolAddress((void**)&hid,  g_hidden);

    const int SMEM_TC = 2 * (128 + 128) * 36 * 4;  // 73728 bytes
    cudaFuncSetAttribute(gemm_tc<128,128,64,32,false>,
                         cudaFuncAttributeMaxDynamicSharedMemorySize, SMEM_TC);
    cudaFuncSetAttribute(gemm_tc<128,128,64,32,true>,
                         cudaFuncAttributeMaxDynamicSharedMemorySize, SMEM_TC);

    const float scale = 0.125f;  // 1/sqrt(64)
    dim3 blk(256);
    dim3 gProj(DD/128, MM/128, 1);
    dim3 gScore(SS/128, SS/128, BH);
    dim3 gPV(1, SS/128, BH);
    dim3 gFF1(DFFN/128, MM/128, 1);
    long long SD  = (long long)SS * DD;
    long long SSq = (long long)SS * SS;

    // ---- Self-attention ----
    gemm_tc<128,128,64,32,false><<<gProj, blk, SMEM_TC>>>(x, DD,0,0, sa_wq, DD,0,0, sa_bq, q, DD,0,0, DD, 1.f, 1);
    gemm_tc<128,128,64,32,false><<<gProj, blk, SMEM_TC>>>(x, DD,0,0, sa_wk, DD,0,0, sa_bk, k, DD,0,0, DD, 1.f, 1);
    gemm_tc<128,128,64,32,false><<<gProj, blk, SMEM_TC>>>(x, DD,0,0, sa_wv, DD,0,0, sa_bv, v, DD,0,0, DD, 1.f, 1);
    gemm_tc<128,128,64,32,false><<<gScore, blk, SMEM_TC>>>(q, DD, SD, DKK, k, DD, SD, DKK, (const float*)0,
                                  sc, SS, (long long)HH*SSq, SSq, DKK, scale, HH);
    softmax_rows<<<BH*SS, blk>>>(sc, 1);
    gemm_nn_tc<128,64,32,32><<<gPV, blk>>>(sc, SS, (long long)HH*SSq, SSq, v, DD, SD, DKK,
                      attn, DD, SD, DKK, SS, HH);
    gemm_tc<128,128,64,32,false><<<gProj, blk, SMEM_TC>>>(attn, DD,0,0, sa_wo, DD,0,0, sa_bo, tmp, DD,0,0, DD, 1.f, 1);
    add_ln_kernel<<<MM, blk>>>(x, tmp, n1_g, n1_b, x1);

    // ---- Cross-attention ----
    gemm_tc<128,128,64,32,false><<<gProj, blk, SMEM_TC>>>(x1,  DD,0,0, ca_in_w,             DD,0,0, ca_in_b,        q, DD,0,0, DD, 1.f, 1);
    gemm_tc<128,128,64,32,false><<<gProj, blk, SMEM_TC>>>(enc, DD,0,0, ca_in_w + (long long)DD*DD,  DD,0,0, ca_in_b + DD,   k, DD,0,0, DD, 1.f, 1);
    gemm_tc<128,128,64,32,false><<<gProj, blk, SMEM_TC>>>(enc, DD,0,0, ca_in_w + 2ll*DD*DD, DD,0,0, ca_in_b + 2*DD, v, DD,0,0, DD, 1.f, 1);
    gemm_tc<128,128,64,32,false><<<gScore, blk, SMEM_TC>>>(q, DD, SD, DKK, k, DD, SD, DKK, (const float*)0,
                                  sc, SS, (long long)HH*SSq, SSq, DKK, scale, HH);
    softmax_rows<<<BH*SS, blk>>>(sc, 0);
    gemm_nn_tc<128,64,32,32><<<gPV, blk>>>(sc, SS, (long long)HH*SSq, SSq, v, DD, SD, DKK,
                      attn, DD, SD, DKK, SS, HH);
    gemm_tc<128,128,64,32,false><<<gProj, blk, SMEM_TC>>>(attn, DD,0,0, ca_out_w, DD,0,0, ca_out_b, tmp, DD,0,0, DD, 1.f, 1);
    add_ln_kernel<<<MM, blk>>>(x1, tmp, n2_g, n2_b, x2);

    // ---- FFN ----
    gemm_tc<128,128,64,32,true ><<<gFF1,  blk, SMEM_TC>>>(x2,  DD,0,0,   ff_w1, DD,0,0,   ff_b1, hid, DFFN,0,0, DD,   1.f, 1);
    gemm_tc<128,128,64,32,false><<<gProj, blk, SMEM_TC>>>(hid, DFFN,0,0, ff_w2, DFFN,0,0, ff_b2, tmp, DD,0,0,   DFFN, 1.f, 1);
    add_ln_kernel<<<MM, blk>>>(x2, tmp, n3_g, n3_b, out);
}

// round 7
// speedup vs baseline: 3.6094x; 1.1487x over previous
#include <cuda_runtime.h>
#include <cuda_bf16.h>
#include <cstdint>
#include <math.h>

// Problem constants
#define BB   4
#define SS   1024
#define DD   1024
#define HH   16
#define DKK  64
#define DFFN 4096
#define MM   (BB*SS)        // 4096 token rows
#define BH   (BB*HH)        // 64

// ---------------------------------------------------------------------------
// Scratch
// ---------------------------------------------------------------------------
__device__ float g_q[MM*DD];
__device__ float g_k[MM*DD];
__device__ float g_v[MM*DD];      // holds V TRANSPOSED: [(b*1024+col)*1024 + t]
__device__ float g_attn[MM*DD];
__device__ float g_tmp[MM*DD];
__device__ float g_x1[MM*DD];
__device__ float g_x2[MM*DD];
__device__ float g_hidden[(long long)MM*DFFN];    // 67MB

// ---------------------------------------------------------------------------
// helpers
// ---------------------------------------------------------------------------
__device__ __forceinline__ unsigned int f2tf32(float f) {
    unsigned int r;
    asm("cvt.rna.tf32.f32 %0, %1;" : "=r"(r) : "f"(f));
    return r;
}

__device__ __forceinline__ void mma_tf32(float (&c)[4],
                                         const unsigned int (&a)[4],
                                         const unsigned int (&b)[2]) {
    asm volatile(
        "mma.sync.aligned.m16n8k8.row.col.f32.tf32.tf32.f32 "
        "{%0,%1,%2,%3}, {%4,%5,%6,%7}, {%8,%9}, {%0,%1,%2,%3};"
        : "+f"(c[0]), "+f"(c[1]), "+f"(c[2]), "+f"(c[3])
        : "r"(a[0]), "r"(a[1]), "r"(a[2]), "r"(a[3]),
          "r"(b[0]), "r"(b[1]));
}

__device__ __forceinline__ void cp16(unsigned int saddr, const float* g) {
    asm volatile("cp.async.cg.shared.global [%0], [%1], 16;\n" :: "r"(saddr), "l"(g));
}
__device__ __forceinline__ void cp_commit() {
    asm volatile("cp.async.commit_group;\n" ::);
}
__device__ __forceinline__ void cp_wait1() {
    asm volatile("cp.async.wait_group 1;\n" ::);
}
__device__ __forceinline__ void cp_wait0() {
    asm volatile("cp.async.wait_group 0;\n" ::);
}

// ---------------------------------------------------------------------------
// Async double-buffered tf32 tensor-core GEMM (TN):
//   C = (A @ B^T) + bias [, relu]
// Fragments are RNA-rounded to tf32 (unbiased) at load time.
// ROUND_OUT: epilogue rounds outputs to the tf32 grid (for flash inputs).
// TRANS_OUT: write V transposed: [(b*1024+col)*1024 + t]  (row = b*1024+t).
// ---------------------------------------------------------------------------
template<int BM, int BN, int WM, int WN, bool RELU, bool ROUND_OUT, bool TRANS_OUT>
__global__ void __launch_bounds__(256, 2) gemm_tc(
    const float* __restrict__ A, int lda, long long sA1, long long sA2,
    const float* __restrict__ B, int ldb, long long sB1, long long sB2,
    const float* __restrict__ bias,
    float* __restrict__ C, int ldc, long long sC1, long long sC2,
    int K, int zdiv)
{
    constexpr int MT  = WM / 16;
    constexpr int NT  = WN / 8;
    constexpr int NWN = BN / WN;

    extern __shared__ float smem[];
    float* AsBase = smem;
    float* BsBase = smem + 2 * BM * 36;

    int z  = blockIdx.z;
    int zb = z / zdiv, zh = z % zdiv;
    A += zb * sA1 + zh * sA2;
    B += zb * sB1 + zh * sB2;
    C += zb * sC1 + zh * sC2;

    const int row0 = blockIdx.y * BM;
    const int col0 = blockIdx.x * BN;
    const int t    = threadIdx.x;
    const int w    = t >> 5;
    const int lane = t & 31;
    const int wm   = w / NWN;
    const int wn   = w % NWN;
    const int gr   = lane >> 2;
    const int gc   = lane & 3;

    const int m0 = t >> 3;
    const int kq = t & 7;

    const float* gA = A + (long long)(row0 + m0) * lda + kq * 4;
    const float* gB = B + (long long)(col0 + m0) * ldb + kq * 4;

    unsigned int aBase = (unsigned int)__cvta_generic_to_shared(AsBase);
    unsigned int bBase = (unsigned int)__cvta_generic_to_shared(BsBase);
    constexpr unsigned int stageA = BM * 36 * 4;
    constexpr unsigned int stageB = BN * 36 * 4;

    float acc[MT][NT][4];
    #pragma unroll
    for (int i = 0; i < MT; i++)
        #pragma unroll
        for (int j = 0; j < NT; j++)
            #pragma unroll
            for (int r = 0; r < 4; r++) acc[i][j][r] = 0.f;

    const int nk = K >> 5;

    #pragma unroll
    for (int i = 0; i < BM / 32; i++)
        cp16(aBase + ((m0 + 32 * i) * 36 + kq * 4) * 4, gA + (long long)(32 * i) * lda);
    #pragma unroll
    for (int i = 0; i < BN / 32; i++)
        cp16(bBase + ((m0 + 32 * i) * 36 + kq * 4) * 4, gB + (long long)(32 * i) * ldb);
    cp_commit();

    for (int it = 0; it < nk; it++) {
        const int cur = it & 1;
        if (it + 1 < nk) {
            const int nxt = cur ^ 1;
            const float* gA2 = gA + (it + 1) * 32;
            const float* gB2 = gB + (it + 1) * 32;
            #pragma unroll
            for (int i = 0; i < BM / 32; i++)
                cp16(aBase + nxt * stageA + ((m0 + 32 * i) * 36 + kq * 4) * 4,
                     gA2 + (long long)(32 * i) * lda);
            #pragma unroll
            for (int i = 0; i < BN / 32; i++)
                cp16(bBase + nxt * stageB + ((m0 + 32 * i) * 36 + kq * 4) * 4,
                     gB2 + (long long)(32 * i) * ldb);
            cp_commit();
            cp_wait1();
        } else {
            cp_wait0();
        }
        __syncthreads();

        const float* Acur = AsBase + cur * (BM * 36);
        const float* Bcur = BsBase + cur * (BN * 36);

        #pragma unroll
        for (int ks = 0; ks < 32; ks += 8) {
            unsigned int af[MT][4];
            unsigned int bf[NT][2];
            #pragma unroll
            for (int mt = 0; mt < MT; mt++) {
                int r = wm * WM + mt * 16 + gr;
                af[mt][0] = f2tf32(Acur[(r    ) * 36 + ks + gc]);
                af[mt][1] = f2tf32(Acur[(r + 8) * 36 + ks + gc]);
                af[mt][2] = f2tf32(Acur[(r    ) * 36 + ks + gc + 4]);
                af[mt][3] = f2tf32(Acur[(r + 8) * 36 + ks + gc + 4]);
            }
            #pragma unroll
            for (int nt = 0; nt < NT; nt++) {
                int n = wn * WN + nt * 8 + gr;
                bf[nt][0] = f2tf32(Bcur[n * 36 + ks + gc]);
                bf[nt][1] = f2tf32(Bcur[n * 36 + ks + gc + 4]);
            }
            #pragma unroll
            for (int mt = 0; mt < MT; mt++)
                #pragma unroll
                for (int nt = 0; nt < NT; nt++)
                    mma_tf32(acc[mt][nt], af[mt], bf[nt]);
        }
        __syncthreads();
    }

    // ---- Epilogue ----
    #pragma unroll
    for (int mt = 0; mt < MT; mt++) {
        #pragma unroll
        for (int nt = 0; nt < NT; nt++) {
            int row = row0 + wm * WM + mt * 16 + gr;
            int col = col0 + wn * WN + nt * 8 + gc * 2;
            float b0 = 0.f, b1 = 0.f;
            if (bias) { b0 = bias[col]; b1 = bias[col + 1]; }
            float v0 = acc[mt][nt][0] + b0;
            float v1 = acc[mt][nt][1] + b1;
            float v2 = acc[mt][nt][2] + b0;
            float v3 = acc[mt][nt][3] + b1;
            if (RELU) {
                v0 = fmaxf(v0, 0.f); v1 = fmaxf(v1, 0.f);
                v2 = fmaxf(v2, 0.f); v3 = fmaxf(v3, 0.f);
            }
            if (ROUND_OUT) {
                v0 = __uint_as_float(f2tf32(v0));
                v1 = __uint_as_float(f2tf32(v1));
                v2 = __uint_as_float(f2tf32(v2));
                v3 = __uint_as_float(f2tf32(v3));
            }
            if (TRANS_OUT) {
                int rb = row >> 10;          // batch
                int tt = row & 1023;         // token within batch
                long long a0 = ((long long)(rb * 1024 + col) << 10) + tt;
                C[a0]            = v0;
                C[a0 + 1024]     = v1;   // col+1
                C[a0 + 8]        = v2;   // row+8
                C[a0 + 1024 + 8] = v3;
            } else {
                *(float2*)(C + (long long)row * ldc + col)       = make_float2(v0, v1);
                *(float2*)(C + (long long)(row + 8) * ldc + col) = make_float2(v2, v3);
            }
        }
    }
}

// ---------------------------------------------------------------------------
// Flash attention: one CTA = 128 q-rows of one (b,h). KV tiles of 64.
//   Q,K: [B*S, D] (head offset h*64), rounded to tf32 grid by producers.
//   VT:  [(b*1024 + col)*1024 + t]  (pre-transposed V)
//   O:   [B*S, D]
// 8 warps; each warp owns 16 q-rows. Scores via m16n8k8 (NT=8 -> 64 cols).
// Online softmax per row; P staged via SMEM; PV via m16n8k8.
// ---------------------------------------------------------------------------
#define FQT 128
#define FKT 64
#define FSB 68

template<bool CAUSAL>
__global__ void __launch_bounds__(256, 2) flash_attn(
    const float* __restrict__ Q, const float* __restrict__ K,
    const float* __restrict__ VT, float* __restrict__ O)
{
    extern __shared__ float sm[];
    float* Kb = sm;                       // [FKT][FSB]  token-major
    float* Vb = sm + FKT * FSB;           // [64][FSB]   dim-major (token minor)
    float* Pb = sm + 2 * FKT * FSB;       // [FQT][FSB]  P (also Q staging)

    const int qi = blockIdx.x;            // 0..7
    const int bh = blockIdx.y;            // 0..63
    const int b  = bh >> 4;
    const int h  = bh & 15;

    const int t    = threadIdx.x;
    const int w    = t >> 5;
    const int lane = t & 31;
    const int gr   = lane >> 2;
    const int gc   = lane & 3;
    const int wrow = w * 16;

    const long long rowbase = (long long)b * SS;
    const float* Qp = Q + (rowbase + qi * FQT) * DD + h * 64;
    const float* Kp = K + rowbase * DD + h * 64;
    const float* Vp = VT + (((long long)(b * 1024 + h * 64)) << 10);
    float* Op = O + (rowbase + qi * FQT) * DD + h * 64;

    // ---- Stage Q tile into Pb, build persistent A-fragments ----
    #pragma unroll
    for (int i = 0; i < 8; i++) {
        int l  = t + i * 256;          // 2048 = 128 rows x 16 float4
        int m  = l >> 4;
        int q4 = l & 15;
        float4 v = *(const float4*)(Qp + (long long)m * DD + q4 * 4);
        *(float4*)&Pb[m * FSB + q4 * 4] = v;
    }
    __syncthreads();

    unsigned int qf[8][4];
    #pragma unroll
    for (int ks = 0; ks < 8; ks++) {
        qf[ks][0] = __float_as_uint(Pb[(wrow + gr    ) * FSB + ks * 8 + gc]);
        qf[ks][1] = __float_as_uint(Pb[(wrow + gr + 8) * FSB + ks * 8 + gc]);
        qf[ks][2] = __float_as_uint(Pb[(wrow + gr    ) * FSB + ks * 8 + gc + 4]);
        qf[ks][3] = __float_as_uint(Pb[(wrow + gr + 8) * FSB + ks * 8 + gc + 4]);
    }
    __syncthreads();

    float o[8][4];
    #pragma unroll
    for (int i = 0; i < 8; i++)
        #pragma unroll
        for (int r = 0; r < 4; r++) o[i][r] = 0.f;
    float m0 = -1e30f, m1 = -1e30f, l0 = 0.f, l1 = 0.f;

    const int rg0 = qi * FQT + wrow + gr;
    const int rg1 = rg0 + 8;
    const int jmax = CAUSAL ? (2 * qi + 1) : (SS / FKT - 1);

    for (int j = 0; j <= jmax; j++) {
        // load K tile [FKT][64]
        #pragma unroll
        for (int i = 0; i < 4; i++) {
            int l  = t + i * 256;      // 1024 = 64 x 16 float4
            int tk = l >> 4;
            int q4 = l & 15;
            float4 v = *(const float4*)(Kp + (long long)(j * FKT + tk) * DD + q4 * 4);
            *(float4*)&Kb[tk * FSB + q4 * 4] = v;
        }
        // load V tile [64 dims][FKT tokens] from VT (contiguous along tokens)
        #pragma unroll
        for (int i = 0; i < 4; i++) {
            int l  = t + i * 256;
            int d  = l >> 4;
            int t4 = l & 15;
            float4 v = *(const float4*)(Vp + (((long long)d) << 10) + j * FKT + t4 * 4);
            *(float4*)&Vb[d * FSB + t4 * 4] = v;
        }
        __syncthreads();

        // ---- scores: s[16 rows][64 cols] per warp ----
        float s[8][4];
        #pragma unroll
        for (int i = 0; i < 8; i++)
            #pragma unroll
            for (int r = 0; r < 4; r++) s[i][r] = 0.f;

        #pragma unroll
        for (int ks = 0; ks < 8; ks++) {
            #pragma unroll
            for (int nt = 0; nt < 8; nt++) {
                unsigned int bf[2];
                bf[0] = __float_as_uint(Kb[(nt * 8 + gr) * FSB + ks * 8 + gc]);
                bf[1] = __float_as_uint(Kb[(nt * 8 + gr) * FSB + ks * 8 + gc + 4]);
                mma_tf32(s[nt], qf[ks], bf);
            }
        }

        // ---- scale + mask + online softmax ----
        float tm0 = -1e30f, tm1 = -1e30f;
        #pragma unroll
        for (int nt = 0; nt < 8; nt++) {
            s[nt][0] *= 0.125f; s[nt][1] *= 0.125f;
            s[nt][2] *= 0.125f; s[nt][3] *= 0.125f;
            if (CAUSAL && j >= 2 * qi) {
                int c0 = j * FKT + nt * 8 + 2 * gc;
                int c1 = c0 + 1;
                if (c0 > rg0) s[nt][0] = -1e30f;
                if (c1 > rg0) s[nt][1] = -1e30f;
                if (c0 > rg1) s[nt][2] = -1e30f;
                if (c1 > rg1) s[nt][3] = -1e30f;
            }
            tm0 = fmaxf(tm0, fmaxf(s[nt][0], s[nt][1]));
            tm1 = fmaxf(tm1, fmaxf(s[nt][2], s[nt][3]));
        }
        tm0 = fmaxf(tm0, __shfl_xor_sync(0xffffffffu, tm0, 1));
        tm0 = fmaxf(tm0, __shfl_xor_sync(0xffffffffu, tm0, 2));
        tm1 = fmaxf(tm1, __shfl_xor_sync(0xffffffffu, tm1, 1));
        tm1 = fmaxf(tm1, __shfl_xor_sync(0xffffffffu, tm1, 2));

        float mn0 = fmaxf(m0, tm0);
        float mn1 = fmaxf(m1, tm1);
        float sc0 = __expf(m0 - mn0);
        float sc1 = __expf(m1 - mn1);
        float ps0 = 0.f, ps1 = 0.f;

        #pragma unroll
        for (int nt = 0; nt < 8; nt++) {
            float p00 = __expf(s[nt][0] - mn0);
            float p01 = __expf(s[nt][1] - mn0);
            float p10 = __expf(s[nt][2] - mn1);
            float p11 = __expf(s[nt][3] - mn1);
            ps0 += p00 + p01;
            ps1 += p10 + p11;
            *(float2*)&Pb[(wrow + gr    ) * FSB + nt * 8 + 2 * gc] = make_float2(p00, p01);
            *(float2*)&Pb[(wrow + gr + 8) * FSB + nt * 8 + 2 * gc] = make_float2(p10, p11);
        }
        ps0 += __shfl_xor_sync(0xffffffffu, ps0, 1);
        ps0 += __shfl_xor_sync(0xffffffffu, ps0, 2);
        ps1 += __shfl_xor_sync(0xffffffffu, ps1, 1);
        ps1 += __shfl_xor_sync(0xffffffffu, ps1, 2);

        l0 = l0 * sc0 + ps0;
        l1 = l1 * sc1 + ps1;
        m0 = mn0; m1 = mn1;

        #pragma unroll
        for (int nt = 0; nt < 8; nt++) {
            o[nt][0] *= sc0; o[nt][1] *= sc0;
            o[nt][2] *= sc1; o[nt][3] *= sc1;
        }
        __syncwarp();

        // ---- PV: o += P[16 x 64] @ V[64 x 64] ----
        #pragma unroll
        for (int ks = 0; ks < 8; ks++) {
            unsigned int pf[4];
            pf[0] = __float_as_uint(Pb[(wrow + gr    ) * FSB + ks * 8 + gc]);
            pf[1] = __float_as_uint(Pb[(wrow + gr + 8) * FSB + ks * 8 + gc]);
            pf[2] = __float_as_uint(Pb[(wrow + gr    ) * FSB + ks * 8 + gc + 4]);
            pf[3] = __float_as_uint(Pb[(wrow + gr + 8) * FSB + ks * 8 + gc + 4]);
            #pragma unroll
            for (int nt = 0; nt < 8; nt++) {
                unsigned int bf[2];
                bf[0] = __float_as_uint(Vb[(nt * 8 + gr) * FSB + ks * 8 + gc]);
                bf[1] = __float_as_uint(Vb[(nt * 8 + gr) * FSB + ks * 8 + gc + 4]);
                mma_tf32(o[nt], pf, bf);
            }
        }
        __syncthreads();
    }

    // ---- epilogue: divide by row sums, write O ----
    float inv0 = 1.f / l0;
    float inv1 = 1.f / l1;
    #pragma unroll
    for (int nt = 0; nt < 8; nt++) {
        int c = nt * 8 + 2 * gc;
        *(float2*)(Op + (long long)(wrow + gr    ) * DD + c) =
            make_float2(o[nt][0] * inv0, o[nt][1] * inv0);
        *(float2*)(Op + (long long)(wrow + gr + 8) * DD + c) =
            make_float2(o[nt][2] * inv1, o[nt][3] * inv1);
    }
}

// ---------------------------------------------------------------------------
// out = LayerNorm(a + b) * g + beta
// ---------------------------------------------------------------------------
__global__ void __launch_bounds__(256) add_ln_kernel(
    const float* __restrict__ A, const float* __restrict__ Bv,
    const float* __restrict__ g, const float* __restrict__ be,
    float* __restrict__ out)
{
    __shared__ float redS[8];
    __shared__ float redQ[8];
    long long row = blockIdx.x;
    int t = threadIdx.x;

    float4 a = *(const float4*)(A  + row * DD + t * 4);
    float4 b = *(const float4*)(Bv + row * DD + t * 4);
    float4 s;
    s.x = a.x + b.x; s.y = a.y + b.y; s.z = a.z + b.z; s.w = a.w + b.w;

    float sum = s.x + s.y + s.z + s.w;
    float sq  = s.x*s.x + s.y*s.y + s.z*s.z + s.w*s.w;
    #pragma unroll
    for (int o = 16; o > 0; o >>= 1) {
        sum += __shfl_xor_sync(0xffffffffu, sum, o);
        sq  += __shfl_xor_sync(0xffffffffu, sq,  o);
    }
    if ((t & 31) == 0) { redS[t >> 5] = sum; redQ[t >> 5] = sq; }
    __syncthreads();
    sum = 0.f; sq = 0.f;
    #pragma unroll
    for (int i = 0; i < 8; i++) { sum += redS[i]; sq += redQ[i]; }

    float mean = sum * (1.0f / DD);
    float var  = sq  * (1.0f / DD) - mean * mean;
    float rstd = rsqrtf(var + 1e-5f);

    float4 gg = *(const float4*)(g  + t * 4);
    float4 bb = *(const float4*)(be + t * 4);
    float4 o;
    o.x = (s.x - mean) * rstd * gg.x + bb.x;
    o.y = (s.y - mean) * rstd * gg.y + bb.y;
    o.z = (s.z - mean) * rstd * gg.z + bb.z;
    o.w = (s.w - mean) * rstd * gg.w + bb.w;
    *(float4*)(out + row * DD + t * 4) = o;
}

// ---------------------------------------------------------------------------
// Launch
// ---------------------------------------------------------------------------
extern "C" void kernel_launch(void* const* d_in, const int* in_sizes, int n_in,
                              void* d_out, int out_size)
{
    const float* x        = (const float*)d_in[0];
    const float* enc      = (const float*)d_in[1];
    const float* sa_wq    = (const float*)d_in[4];
    const float* sa_bq    = (const float*)d_in[5];
    const float* sa_wk    = (const float*)d_in[6];
    const float* sa_bk    = (const float*)d_in[7];
    const float* sa_wv    = (const float*)d_in[8];
    const float* sa_bv    = (const float*)d_in[9];
    const float* sa_wo    = (const float*)d_in[10];
    const float* sa_bo    = (const float*)d_in[11];
    const float* ca_in_w  = (const float*)d_in[12];
    const float* ca_in_b  = (const float*)d_in[13];
    const float* ca_out_w = (const float*)d_in[14];
    const float* ca_out_b = (const float*)d_in[15];
    const float* ff_w1    = (const float*)d_in[16];
    const float* ff_b1    = (const float*)d_in[17];
    const float* ff_w2    = (const float*)d_in[18];
    const float* ff_b2    = (const float*)d_in[19];
    const float* n1_g     = (const float*)d_in[20];
    const float* n1_b     = (const float*)d_in[21];
    const float* n2_g     = (const float*)d_in[22];
    const float* n2_b     = (const float*)d_in[23];
    const float* n3_g     = (const float*)d_in[24];
    const float* n3_b     = (const float*)d_in[25];
    float* out = (float*)d_out;

    float *q, *k, *v, *attn, *tmp, *x1, *x2, *hid;
    cudaGetSymbolAddress((void**)&q,    g_q);
    cudaGetSymbolAddress((void**)&k,    g_k);
    cudaGetSymbolAddress((void**)&v,    g_v);
    cudaGetSymbolAddress((void**)&attn, g_attn);
    cudaGetSymbolAddress((void**)&tmp,  g_tmp);
    cudaGetSymbolAddress((void**)&x1,   g_x1);
    cudaGetSymbolAddress((void**)&x2,   g_x2);
    cudaGetSymbolAddress((void**)&hid,  g_hidden);

    const int SMEM_TC = 2 * (128 + 128) * 36 * 4;       // 73728 bytes
    const int SMEM_FL = (FKT + 64 + FQT) * FSB * 4;     // 69632 bytes
    cudaFuncSetAttribute(gemm_tc<128,128,64,32,false,false,false>,
                         cudaFuncAttributeMaxDynamicSharedMemorySize, SMEM_TC);
    cudaFuncSetAttribute(gemm_tc<128,128,64,32,true,false,false>,
                         cudaFuncAttributeMaxDynamicSharedMemorySize, SMEM_TC);
    cudaFuncSetAttribute(gemm_tc<128,128,64,32,false,true,false>,
                         cudaFuncAttributeMaxDynamicSharedMemorySize, SMEM_TC);
    cudaFuncSetAttribute(gemm_tc<128,128,64,32,false,true,true>,
                         cudaFuncAttributeMaxDynamicSharedMemorySize, SMEM_TC);
    cudaFuncSetAttribute(flash_attn<true>,
                         cudaFuncAttributeMaxDynamicSharedMemorySize, SMEM_FL);
    cudaFuncSetAttribute(flash_attn<false>,
                         cudaFuncAttributeMaxDynamicSharedMemorySize, SMEM_FL);

    dim3 blk(256);
    dim3 gProj(DD/128, MM/128, 1);
    dim3 gFF1(DFFN/128, MM/128, 1);
    dim3 gFlash(SS/128, BH, 1);

    // ---- Self-attention ----
    gemm_tc<128,128,64,32,false,true,false><<<gProj, blk, SMEM_TC>>>(x, DD,0,0, sa_wq, DD,0,0, sa_bq, q, DD,0,0, DD, 1);
    gemm_tc<128,128,64,32,false,true,false><<<gProj, blk, SMEM_TC>>>(x, DD,0,0, sa_wk, DD,0,0, sa_bk, k, DD,0,0, DD, 1);
    gemm_tc<128,128,64,32,false,true,true ><<<gProj, blk, SMEM_TC>>>(x, DD,0,0, sa_wv, DD,0,0, sa_bv, v, DD,0,0, DD, 1);
    flash_attn<true><<<gFlash, blk, SMEM_FL>>>(q, k, v, attn);
    gemm_tc<128,128,64,32,false,false,false><<<gProj, blk, SMEM_TC>>>(attn, DD,0,0, sa_wo, DD,0,0, sa_bo, tmp, DD,0,0, DD, 1);
    add_ln_kernel<<<MM, blk>>>(x, tmp, n1_g, n1_b, x1);

    // ---- Cross-attention ----
    gemm_tc<128,128,64,32,false,true,false><<<gProj, blk, SMEM_TC>>>(x1,  DD,0,0, ca_in_w,             DD,0,0, ca_in_b,        q, DD,0,0, DD, 1);
    gemm_tc<128,128,64,32,false,true,false><<<gProj, blk, SMEM_TC>>>(enc, DD,0,0, ca_in_w + (long long)DD*DD,  DD,0,0, ca_in_b + DD,   k, DD,0,0, DD, 1);
    gemm_tc<128,128,64,32,false,true,true ><<<gProj, blk, SMEM_TC>>>(enc, DD,0,0, ca_in_w + 2ll*DD*DD, DD,0,0, ca_in_b + 2*DD, v, DD,0,0, DD, 1);
    flash_attn<false><<<gFlash, blk, SMEM_FL>>>(q, k, v, attn);
    gemm_tc<128,128,64,32,false,false,false><<<gProj, blk, SMEM_TC>>>(attn, DD,0,0, ca_out_w, DD,0,0, ca_out_b, tmp, DD,0,0, DD, 1);
    add_ln_kernel<<<MM, blk>>>(x1, tmp, n2_g, n2_b, x2);

    // ---- FFN ----
    gemm_tc<128,128,64,32,true,false,false ><<<gFF1,  blk, SMEM_TC>>>(x2,  DD,0,0,   ff_w1, DD,0,0,   ff_b1, hid, DFFN,0,0, DD,   1);
    gemm_tc<128,128,64,32,false,false,false><<<gProj, blk, SMEM_TC>>>(hid, DFFN,0,0, ff_w2, DFFN,0,0, ff_b2, tmp, DD,0,0,   DFFN, 1);
    add_ln_kernel<<<MM, blk>>>(x2, tmp, n3_g, n3_b, out);
}